// round 6
// baseline (speedup 1.0000x reference)
#include <cuda_runtime.h>

// Problem constants (fixed by the dataset)
#define INDIM 256
#define HID   128     // H * F1
#define NH    4
#define FD    32
#define C2    40      // classes
#define C2P   64      // padded cols for gemm2
#define NMAXN 100000
#define EMAXE 1600000

#define NEG_INF __int_as_float(0xff800000)

// -------- scratch (static device globals; no allocations anywhere) --------
__device__ float g_h1  [(size_t)NMAXN * HID];
__device__ float g_out1[(size_t)NMAXN * HID];
__device__ float g_h2  [(size_t)NMAXN * C2];
__device__ float g_el1 [NMAXN * NH];
__device__ float g_er1 [NMAXN * NH];
__device__ float g_el2 [NMAXN];
__device__ float g_er2 [NMAXN];
__device__ float g_e1  [(size_t)EMAXE * NH];    // slow-path scratch only
__device__ float g_e2  [EMAXE];                 // slow-path scratch only
__device__ float g_W2p [HID * C2P];
// CSR by dst
__device__ int   g_deg [NMAXN];
__device__ int   g_off [NMAXN + 1];
__device__ int   g_cur [NMAXN];
__device__ int   g_part[256];
__device__ int   g_csr_src[EMAXE];

// -------- helpers --------
__device__ __forceinline__ float lrelu(float v) { return v > 0.f ? v : 0.2f * v; }
__device__ __forceinline__ float elu(float v)   { return v > 0.f ? v : (__expf(v) - 1.f); }

// ============================================================================
// GEMM1 + fused elr1 (unchanged from R5)
// ============================================================================
template <int K>
__global__ __launch_bounds__(256)
void gemm128_elr(const float* __restrict__ A, const float* __restrict__ W,
                 float* __restrict__ C,
                 const float* __restrict__ al, const float* __restrict__ ar,
                 int nrows)
{
    __shared__ float As[16][136];
    __shared__ float Ws[16][128];

    const int tid = threadIdx.x;
    const int tx  = tid & 15;
    const int ty  = tid >> 4;
    const int r0  = blockIdx.x * 128;

    float acc[8][8];
#pragma unroll
    for (int i = 0; i < 8; i++)
#pragma unroll
        for (int j = 0; j < 8; j++) acc[i][j] = 0.f;

    for (int kt = 0; kt < K; kt += 16) {
#pragma unroll
        for (int i = 0; i < 2; i++) {
            int idx = tid + i * 256;
            int r   = idx >> 2;
            int kq  = (idx & 3) * 4;
            float4 v = make_float4(0.f, 0.f, 0.f, 0.f);
            int row = r0 + r;
            if (row < nrows)
                v = *(const float4*)(A + (size_t)row * K + kt + kq);
            As[kq + 0][r] = v.x; As[kq + 1][r] = v.y;
            As[kq + 2][r] = v.z; As[kq + 3][r] = v.w;
        }
#pragma unroll
        for (int i = 0; i < 2; i++) {
            int idx = tid + i * 256;
            int kr  = idx >> 5;
            int cq  = (idx & 31) * 4;
            *(float4*)(&Ws[kr][cq]) =
                *(const float4*)(W + (size_t)(kt + kr) * 128 + cq);
        }
        __syncthreads();

#pragma unroll
        for (int k = 0; k < 16; k++) {
            float4 a0 = *(const float4*)(&As[k][ty * 8]);
            float4 a1 = *(const float4*)(&As[k][ty * 8 + 4]);
            float4 w0 = *(const float4*)(&Ws[k][tx * 8]);
            float4 w1 = *(const float4*)(&Ws[k][tx * 8 + 4]);
            float a[8] = {a0.x, a0.y, a0.z, a0.w, a1.x, a1.y, a1.z, a1.w};
            float w[8] = {w0.x, w0.y, w0.z, w0.w, w1.x, w1.y, w1.z, w1.w};
#pragma unroll
            for (int i = 0; i < 8; i++)
#pragma unroll
                for (int j = 0; j < 8; j++) acc[i][j] += a[i] * w[j];
        }
        __syncthreads();
    }

#pragma unroll
    for (int i = 0; i < 8; i++) {
        int row = r0 + ty * 8 + i;
        if (row >= nrows) continue;
        float* cp = C + (size_t)row * 128 + tx * 8;
        *(float4*)(cp)     = make_float4(acc[i][0], acc[i][1], acc[i][2], acc[i][3]);
        *(float4*)(cp + 4) = make_float4(acc[i][4], acc[i][5], acc[i][6], acc[i][7]);
    }

    const int lane = tid & 31;
    float alv[8], arv[8];
#pragma unroll
    for (int j = 0; j < 8; j++) {
        alv[j] = al[tx * 8 + j];
        arv[j] = ar[tx * 8 + j];
    }
    const int head = (lane & 15) >> 2;
#pragma unroll
    for (int i = 0; i < 8; i++) {
        float pel = 0.f, per = 0.f;
#pragma unroll
        for (int j = 0; j < 8; j++) {
            pel += acc[i][j] * alv[j];
            per += acc[i][j] * arv[j];
        }
        pel += __shfl_xor_sync(0xffffffffu, pel, 1);
        pel += __shfl_xor_sync(0xffffffffu, pel, 2);
        per += __shfl_xor_sync(0xffffffffu, per, 1);
        per += __shfl_xor_sync(0xffffffffu, per, 2);
        int row = r0 + ty * 8 + i;
        if ((lane & 3) == 0 && row < nrows) {
            g_el1[row * 4 + head] = pel;
            g_er1[row * 4 + head] = per;
        }
    }
}

// ============================================================================
// GEMM2 + fused elr2, with row offset for chunked pipelining
// ============================================================================
template <int K, int NC, int NCREAL>
__global__ __launch_bounds__(256)
void gemm_tiled_elr(const float* __restrict__ A, const float* __restrict__ W,
                    float* __restrict__ C,
                    const float* __restrict__ al, const float* __restrict__ ar,
                    int row0, int nrows, int ostride)
{
    constexpr int CPT = NC / 32;
    __shared__ float fsh[64][32];
    __shared__ float wsh[32][NC];

    const int tid = threadIdx.x;
    const int r0  = row0 + blockIdx.x * 64;
    const int cx  = tid & 31;
    const int ry  = tid >> 5;

    float acc[8][CPT];
#pragma unroll
    for (int i = 0; i < 8; i++)
#pragma unroll
        for (int j = 0; j < CPT; j++) acc[i][j] = 0.f;

    for (int kt = 0; kt < K; kt += 32) {
#pragma unroll
        for (int i = 0; i < 2; i++) {
            int idx = tid + i * 256;
            int r = idx >> 3, kq = idx & 7;
            int row = r0 + r;
            float4 v = make_float4(0.f, 0.f, 0.f, 0.f);
            if (row < nrows)
                v = *(const float4*)(A + (size_t)row * K + kt + kq * 4);
            *(float4*)(&fsh[r][kq * 4]) = v;
        }
#pragma unroll
        for (int i = 0; i < CPT; i++) {
            int idx = tid + i * 256;
            int kr = idx / (NC / 4), cq = idx % (NC / 4);
            *(float4*)(&wsh[kr][cq * 4]) =
                *(const float4*)(W + (size_t)(kt + kr) * NC + cq * 4);
        }
        __syncthreads();

#pragma unroll
        for (int k = 0; k < 32; k++) {
            float2 wv = *(const float2*)(&wsh[k][cx * 2]);
#pragma unroll
            for (int i = 0; i < 8; i++) {
                float f = fsh[ry * 8 + i][k];
                acc[i][0] += f * wv.x;
                acc[i][1] += f * wv.y;
            }
        }
        __syncthreads();
    }

    int c0 = cx * 2, c1 = cx * 2 + 1;
    float al0 = (c0 < NCREAL) ? al[c0] : 0.f;
    float al1v = (c1 < NCREAL) ? al[c1] : 0.f;
    float ar0 = (c0 < NCREAL) ? ar[c0] : 0.f;
    float ar1v = (c1 < NCREAL) ? ar[c1] : 0.f;

#pragma unroll
    for (int i = 0; i < 8; i++) {
        int row = r0 + ry * 8 + i;
        bool ok = row < nrows;
        if (ok) {
            if (c0 < NCREAL) C[(size_t)row * ostride + c0] = acc[i][0];
            if (c1 < NCREAL) C[(size_t)row * ostride + c1] = acc[i][1];
        }
        float pel = acc[i][0] * al0 + acc[i][1] * al1v;
        float per = acc[i][0] * ar0 + acc[i][1] * ar1v;
#pragma unroll
        for (int o = 16; o; o >>= 1) {
            pel += __shfl_xor_sync(0xffffffffu, pel, o);
            per += __shfl_xor_sync(0xffffffffu, per, o);
        }
        if (cx == 0 && ok) {
            g_el2[row] = pel;
            g_er2[row] = per;
        }
    }
}

// ============================================================================
// CSR build
// ============================================================================
__global__ void zero_deg(int n)
{
    int i = blockIdx.x * blockDim.x + threadIdx.x;
    if (i < n) g_deg[i] = 0;
}

__global__ void count_kernel(const int* __restrict__ dst, int e)
{
    int i = blockIdx.x * blockDim.x + threadIdx.x;
    if (i < e) atomicAdd(&g_deg[dst[i]], 1);
}

__global__ __launch_bounds__(1024)
void scan_local(int n)
{
    __shared__ int sh[1024];
    int t = threadIdx.x;
    int i = blockIdx.x * 1024 + t;
    int val = (i < n) ? g_deg[i] : 0;
    sh[t] = val;
    __syncthreads();
#pragma unroll
    for (int d = 1; d < 1024; d <<= 1) {
        int x = (t >= d) ? sh[t - d] : 0;
        __syncthreads();
        sh[t] += x;
        __syncthreads();
    }
    if (i < n) g_off[i] = sh[t] - val;
    if (t == 1023) g_part[blockIdx.x] = sh[1023];
}

__global__ void scan_part(int nblk, int n)
{
    if (threadIdx.x != 0 || blockIdx.x != 0) return;
    int run = 0;
    for (int b = 0; b < nblk; b++) {
        int v = g_part[b];
        g_part[b] = run;
        run += v;
    }
    g_off[n] = run;
}

__global__ void add_part(int n)
{
    int i = blockIdx.x * blockDim.x + threadIdx.x;
    if (i >= n) return;
    int o = g_off[i] + g_part[i >> 10];
    g_off[i] = o;
    g_cur[i] = o;
}

__global__ void scatter_kernel(const int* __restrict__ src, const int* __restrict__ dst, int e)
{
    int i = blockIdx.x * blockDim.x + threadIdx.x;
    if (i >= e) return;
    int d = dst[i];
    int pos = atomicAdd(&g_cur[d], 1);
    g_csr_src[pos] = src[i];
}

__global__ void pack_W2(const float* __restrict__ W2)
{
    int i = blockIdx.x * blockDim.x + threadIdx.x;
    if (i >= HID * C2P) return;
    int k = i / C2P, c = i % C2P;
    g_W2p[i] = (c < C2) ? W2[k * C2 + c] : 0.f;
}

// ============================================================================
// Layer 1: warp per node, node range [node0, node1)
// Gather loop hand-batched 4-wide for MLP.
// ============================================================================
__global__ __launch_bounds__(256)
void gat1_kernel(const float* __restrict__ b1, int node0, int node1)
{
    __shared__ float s_alpha[8][32][4];
    __shared__ int   s_src[8][32];

    int w    = threadIdx.x >> 5;
    int node = node0 + ((blockIdx.x * blockDim.x + threadIdx.x) >> 5);
    int lane = threadIdx.x & 31;
    if (node >= node1) return;

    int off = g_off[node];
    int deg = g_off[node + 1] - off;
    int head = lane >> 3;

    float4 erd = *(const float4*)(g_er1 + (size_t)node * 4);
    float4 acc = make_float4(0.f, 0.f, 0.f, 0.f);

    if (deg <= 32) {
        // softmax fully in registers
        bool valid = lane < deg;
        int s = 0;
        float4 e4 = make_float4(NEG_INF, NEG_INF, NEG_INF, NEG_INF);
        if (valid) {
            s = g_csr_src[off + lane];
            float4 a = *(const float4*)(g_el1 + (size_t)s * 4);
            e4.x = lrelu(a.x + erd.x); e4.y = lrelu(a.y + erd.y);
            e4.z = lrelu(a.z + erd.z); e4.w = lrelu(a.w + erd.w);
        }
        float4 mx = e4;
#pragma unroll
        for (int o = 16; o; o >>= 1) {
            mx.x = fmaxf(mx.x, __shfl_xor_sync(0xffffffffu, mx.x, o));
            mx.y = fmaxf(mx.y, __shfl_xor_sync(0xffffffffu, mx.y, o));
            mx.z = fmaxf(mx.z, __shfl_xor_sync(0xffffffffu, mx.z, o));
            mx.w = fmaxf(mx.w, __shfl_xor_sync(0xffffffffu, mx.w, o));
        }
        float4 ee = make_float4(0.f, 0.f, 0.f, 0.f);
        if (valid) {
            ee.x = __expf(e4.x - mx.x); ee.y = __expf(e4.y - mx.y);
            ee.z = __expf(e4.z - mx.z); ee.w = __expf(e4.w - mx.w);
        }
        float4 sm = ee;
#pragma unroll
        for (int o = 16; o; o >>= 1) {
            sm.x += __shfl_xor_sync(0xffffffffu, sm.x, o);
            sm.y += __shfl_xor_sync(0xffffffffu, sm.y, o);
            sm.z += __shfl_xor_sync(0xffffffffu, sm.z, o);
            sm.w += __shfl_xor_sync(0xffffffffu, sm.w, o);
        }
        float4 al4 = make_float4(0.f, 0.f, 0.f, 0.f);
        if (valid) {
            al4.x = ee.x / sm.x; al4.y = ee.y / sm.y;
            al4.z = ee.z / sm.z; al4.w = ee.w / sm.w;
        }
        s_src[w][lane] = s;
        *(float4*)(&s_alpha[w][lane][0]) = al4;
        __syncwarp();

        // gather, 4-wide batches (independent LDG.128s in flight)
        int q = 0;
        for (; q + 4 <= deg; q += 4) {
            int   s0 = s_src[w][q + 0], s1 = s_src[w][q + 1];
            int   s2 = s_src[w][q + 2], s3 = s_src[w][q + 3];
            float a0 = s_alpha[w][q + 0][head], a1 = s_alpha[w][q + 1][head];
            float a2 = s_alpha[w][q + 2][head], a3 = s_alpha[w][q + 3][head];
            float4 h0 = *(const float4*)(g_h1 + (size_t)s0 * HID + lane * 4);
            float4 h1 = *(const float4*)(g_h1 + (size_t)s1 * HID + lane * 4);
            float4 h2 = *(const float4*)(g_h1 + (size_t)s2 * HID + lane * 4);
            float4 h3 = *(const float4*)(g_h1 + (size_t)s3 * HID + lane * 4);
            acc.x += a0 * h0.x + a1 * h1.x + a2 * h2.x + a3 * h3.x;
            acc.y += a0 * h0.y + a1 * h1.y + a2 * h2.y + a3 * h3.y;
            acc.z += a0 * h0.z + a1 * h1.z + a2 * h2.z + a3 * h3.z;
            acc.w += a0 * h0.w + a1 * h1.w + a2 * h2.w + a3 * h3.w;
        }
        for (; q < deg; q++) {
            int   sq = s_src[w][q];
            float a  = s_alpha[w][q][head];
            float4 hv = *(const float4*)(g_h1 + (size_t)sq * HID + lane * 4);
            acc.x += a * hv.x; acc.y += a * hv.y;
            acc.z += a * hv.z; acc.w += a * hv.w;
        }
    } else {
        // slow path (deg > 32, extremely rare)
        float4 mx = make_float4(NEG_INF, NEG_INF, NEG_INF, NEG_INF);
        for (int base = 0; base < deg; base += 32) {
            int j = base + lane;
            if (j < deg) {
                int s = g_csr_src[off + j];
                float4 a = *(const float4*)(g_el1 + (size_t)s * 4);
                float4 e4;
                e4.x = lrelu(a.x + erd.x); e4.y = lrelu(a.y + erd.y);
                e4.z = lrelu(a.z + erd.z); e4.w = lrelu(a.w + erd.w);
                *(float4*)(g_e1 + (size_t)(off + j) * 4) = e4;
                mx.x = fmaxf(mx.x, e4.x); mx.y = fmaxf(mx.y, e4.y);
                mx.z = fmaxf(mx.z, e4.z); mx.w = fmaxf(mx.w, e4.w);
            }
        }
#pragma unroll
        for (int o = 16; o; o >>= 1) {
            mx.x = fmaxf(mx.x, __shfl_xor_sync(0xffffffffu, mx.x, o));
            mx.y = fmaxf(mx.y, __shfl_xor_sync(0xffffffffu, mx.y, o));
            mx.z = fmaxf(mx.z, __shfl_xor_sync(0xffffffffu, mx.z, o));
            mx.w = fmaxf(mx.w, __shfl_xor_sync(0xffffffffu, mx.w, o));
        }
        float4 sm = make_float4(0.f, 0.f, 0.f, 0.f);
        for (int base = 0; base < deg; base += 32) {
            int j = base + lane;
            if (j < deg) {
                float4 e4 = *(const float4*)(g_e1 + (size_t)(off + j) * 4);
                e4.x = __expf(e4.x - mx.x); e4.y = __expf(e4.y - mx.y);
                e4.z = __expf(e4.z - mx.z); e4.w = __expf(e4.w - mx.w);
                *(float4*)(g_e1 + (size_t)(off + j) * 4) = e4;
                sm.x += e4.x; sm.y += e4.y; sm.z += e4.z; sm.w += e4.w;
            }
        }
#pragma unroll
        for (int o = 16; o; o >>= 1) {
            sm.x += __shfl_xor_sync(0xffffffffu, sm.x, o);
            sm.y += __shfl_xor_sync(0xffffffffu, sm.y, o);
            sm.z += __shfl_xor_sync(0xffffffffu, sm.z, o);
            sm.w += __shfl_xor_sync(0xffffffffu, sm.w, o);
        }
        float invh = 1.f / ((head == 0) ? sm.x : (head == 1) ? sm.y : (head == 2) ? sm.z : sm.w);

        for (int base = 0; base < deg; base += 32) {
            int cnt = min(32, deg - base);
            int j = base + lane;
            int s = 0;
            float4 ee = make_float4(0.f, 0.f, 0.f, 0.f);
            if (j < deg) {
                s = g_csr_src[off + j];
                ee = *(const float4*)(g_e1 + (size_t)(off + j) * 4);
            }
            s_src[w][lane] = s;
            *(float4*)(&s_alpha[w][lane][0]) = ee;
            __syncwarp();
            for (int q = 0; q < cnt; q++) {
                int   sq = s_src[w][q];
                float a  = s_alpha[w][q][head] * invh;
                float4 hv = *(const float4*)(g_h1 + (size_t)sq * HID + lane * 4);
                acc.x += a * hv.x; acc.y += a * hv.y;
                acc.z += a * hv.z; acc.w += a * hv.w;
            }
            __syncwarp();
        }
    }

    float4 bb = *(const float4*)(b1 + lane * 4);
    float4 o;
    o.x = elu(acc.x + bb.x); o.y = elu(acc.y + bb.y);
    o.z = elu(acc.z + bb.z); o.w = elu(acc.w + bb.w);
    *(float4*)(g_out1 + (size_t)node * HID + lane * 4) = o;
}

// ============================================================================
// Layer 2: warp per node (1 head, C=40), gather batched 4-wide
// ============================================================================
__global__ __launch_bounds__(256)
void gat2_kernel(float* __restrict__ out, const float* __restrict__ b2, int n)
{
    __shared__ float s_a[8][32];
    __shared__ int   s_src[8][32];

    int w    = threadIdx.x >> 5;
    int node = (blockIdx.x * blockDim.x + threadIdx.x) >> 5;
    int lane = threadIdx.x & 31;
    if (node >= n) return;

    int off = g_off[node];
    int deg = g_off[node + 1] - off;
    float erd = g_er2[node];

    float acc0 = 0.f, acc1 = 0.f;

    if (deg <= 32) {
        bool valid = lane < deg;
        int s = 0;
        float e = NEG_INF;
        if (valid) {
            s = g_csr_src[off + lane];
            e = lrelu(g_el2[s] + erd);
        }
        float mx = e;
#pragma unroll
        for (int o = 16; o; o >>= 1)
            mx = fmaxf(mx, __shfl_xor_sync(0xffffffffu, mx, o));
        float ee = valid ? __expf(e - mx) : 0.f;
        float sm = ee;
#pragma unroll
        for (int o = 16; o; o >>= 1)
            sm += __shfl_xor_sync(0xffffffffu, sm, o);
        float alpha = valid ? (ee / sm) : 0.f;

        s_src[w][lane] = s;
        s_a[w][lane] = alpha;
        __syncwarp();

        int q = 0;
        for (; q + 4 <= deg; q += 4) {
            int   s0 = s_src[w][q + 0], s1 = s_src[w][q + 1];
            int   s2 = s_src[w][q + 2], s3 = s_src[w][q + 3];
            float a0 = s_a[w][q + 0], a1 = s_a[w][q + 1];
            float a2 = s_a[w][q + 2], a3 = s_a[w][q + 3];
            const float* p0 = g_h2 + (size_t)s0 * C2;
            const float* p1 = g_h2 + (size_t)s1 * C2;
            const float* p2 = g_h2 + (size_t)s2 * C2;
            const float* p3 = g_h2 + (size_t)s3 * C2;
            float v0 = p0[lane], v1 = p1[lane], v2 = p2[lane], v3 = p3[lane];
            acc0 += a0 * v0 + a1 * v1 + a2 * v2 + a3 * v3;
            if (lane < 8) {
                float u0 = p0[32 + lane], u1 = p1[32 + lane];
                float u2 = p2[32 + lane], u3 = p3[32 + lane];
                acc1 += a0 * u0 + a1 * u1 + a2 * u2 + a3 * u3;
            }
        }
        for (; q < deg; q++) {
            int   sq = s_src[w][q];
            float a  = s_a[w][q];
            const float* hp = g_h2 + (size_t)sq * C2;
            acc0 += a * hp[lane];
            if (lane < 8) acc1 += a * hp[32 + lane];
        }
    } else {
        float mx = NEG_INF;
        for (int base = 0; base < deg; base += 32) {
            int j = base + lane;
            if (j < deg) {
                int s = g_csr_src[off + j];
                float e = lrelu(g_el2[s] + erd);
                g_e2[off + j] = e;
                mx = fmaxf(mx, e);
            }
        }
#pragma unroll
        for (int o = 16; o; o >>= 1)
            mx = fmaxf(mx, __shfl_xor_sync(0xffffffffu, mx, o));
        float sm = 0.f;
        for (int base = 0; base < deg; base += 32) {
            int j = base + lane;
            if (j < deg) {
                float ee = __expf(g_e2[off + j] - mx);
                g_e2[off + j] = ee;
                sm += ee;
            }
        }
#pragma unroll
        for (int o = 16; o; o >>= 1)
            sm += __shfl_xor_sync(0xffffffffu, sm, o);
        float inv = 1.f / sm;

        for (int base = 0; base < deg; base += 32) {
            int cnt = min(32, deg - base);
            int j = base + lane;
            int s = 0; float ee = 0.f;
            if (j < deg) {
                s = g_csr_src[off + j];
                ee = g_e2[off + j];
            }
            s_src[w][lane] = s;
            s_a[w][lane] = ee * inv;
            __syncwarp();
            for (int q = 0; q < cnt; q++) {
                int   sq = s_src[w][q];
                float a  = s_a[w][q];
                const float* hp = g_h2 + (size_t)sq * C2;
                acc0 += a * hp[lane];
                if (lane < 8) acc1 += a * hp[32 + lane];
            }
            __syncwarp();
        }
    }

    out[(size_t)node * C2 + lane] = acc0 + b2[lane];
    if (lane < 8)
        out[(size_t)node * C2 + 32 + lane] = acc1 + b2[32 + lane];
}

// ============================================================================
// launch — CSR ∥ gemm1 fork; gemm2(chunk0) ∥ gat1(chunk1) pipeline
// ============================================================================
extern "C" void kernel_launch(void* const* d_in, const int* in_sizes, int n_in,
                              void* d_out, int out_size)
{
    const float* feat = (const float*)d_in[0];
    const int*   src  = (const int*)  d_in[1];
    const int*   dst  = (const int*)  d_in[2];
    const float* W1   = (const float*)d_in[3];
    const float* al1  = (const float*)d_in[4];
    const float* ar1  = (const float*)d_in[5];
    const float* b1   = (const float*)d_in[6];
    const float* W2   = (const float*)d_in[7];
    const float* al2  = (const float*)d_in[8];
    const float* ar2  = (const float*)d_in[9];
    const float* b2   = (const float*)d_in[10];
    float* out = (float*)d_out;

    const int n = in_sizes[0] / INDIM;   // 100000
    const int e = in_sizes[1];           // 1600000

    float *p_h1 = 0, *p_out1 = 0, *p_h2 = 0, *p_W2p = 0;
    cudaGetSymbolAddress((void**)&p_h1,   g_h1);
    cudaGetSymbolAddress((void**)&p_out1, g_out1);
    cudaGetSymbolAddress((void**)&p_h2,   g_h2);
    cudaGetSymbolAddress((void**)&p_W2p,  g_W2p);

    static cudaStream_t s2 = 0;
    static cudaEvent_t ev_fork = 0, ev_join = 0, ev_g1a = 0, ev_g2a = 0;
    if (!s2) {
        cudaStreamCreateWithFlags(&s2, cudaStreamNonBlocking);
        cudaEventCreateWithFlags(&ev_fork, cudaEventDisableTiming);
        cudaEventCreateWithFlags(&ev_join, cudaEventDisableTiming);
        cudaEventCreateWithFlags(&ev_g1a,  cudaEventDisableTiming);
        cudaEventCreateWithFlags(&ev_g2a,  cudaEventDisableTiming);
    }

    const int TB = 256;
    const int nblk_scan = (n + 1023) / 1024;

    // fork: CSR build + pack_W2 on s2, concurrent with gemm1
    cudaEventRecord(ev_fork, 0);
    cudaStreamWaitEvent(s2, ev_fork, 0);

    zero_deg<<<(n + TB - 1) / TB, TB, 0, s2>>>(n);
    count_kernel<<<(e + TB - 1) / TB, TB, 0, s2>>>(dst, e);
    scan_local<<<nblk_scan, 1024, 0, s2>>>(n);
    scan_part<<<1, 32, 0, s2>>>(nblk_scan, n);
    add_part<<<(n + TB - 1) / TB, TB, 0, s2>>>(n);
    scatter_kernel<<<(e + TB - 1) / TB, TB, 0, s2>>>(src, dst, e);
    pack_W2<<<(HID * C2P + TB - 1) / TB, TB, 0, s2>>>(W2);
    cudaEventRecord(ev_join, s2);

    // default stream: layer-1 projection (+fused elr1)
    gemm128_elr<INDIM><<<(n + 127) / 128, 256>>>(feat, W1, p_h1, al1, ar1, n);
    cudaStreamWaitEvent(0, ev_join, 0);

    // ---- chunked layer-1 aggregation ∥ layer-2 projection ----
    int c0 = ((n / 2) + 63) & ~63;       // chunk boundary, multiple of 64
    if (c0 > n) c0 = n;

    gat1_kernel<<<(c0 * 32 + TB - 1) / TB, TB>>>(b1, 0, c0);
    cudaEventRecord(ev_g1a, 0);
    cudaStreamWaitEvent(s2, ev_g1a, 0);
    gemm_tiled_elr<HID, C2P, C2><<<(c0 + 63) / 64, 256, 0, s2>>>
        (p_out1, p_W2p, p_h2, al2, ar2, 0, c0, C2);
    cudaEventRecord(ev_g2a, s2);

    gat1_kernel<<<((n - c0) * 32 + TB - 1) / TB, TB>>>(b1, c0, n);

    cudaStreamWaitEvent(0, ev_g2a, 0);
    gemm_tiled_elr<HID, C2P, C2><<<(n - c0 + 63) / 64, 256>>>
        (p_out1, p_W2p, p_h2, al2, ar2, c0, n, C2);

    // layer-2 aggregation (needs both h2 chunks — ordered above)
    gat2_kernel<<<(n * 32 + TB - 1) / TB, TB>>>(out, b2, n);
}

// round 7
// speedup vs baseline: 1.0220x; 1.0220x over previous
#include <cuda_runtime.h>

// Problem constants (fixed by the dataset)
#define INDIM 256
#define HID   128     // H * F1
#define NH    4
#define FD    32
#define C2    40      // classes
#define C2P   64      // padded cols for gemm2 / h2 row stride
#define NMAXN 100000
#define EMAXE 1600000

#define NEG_INF __int_as_float(0xff800000)

// -------- scratch (static device globals; no allocations anywhere) --------
__device__ float g_h1  [(size_t)NMAXN * HID];
__device__ float g_out1[(size_t)NMAXN * HID];
__device__ float g_h2  [(size_t)NMAXN * C2P];   // padded rows (256B aligned)
__device__ float g_el1 [NMAXN * NH];
__device__ float g_er1 [NMAXN * NH];
__device__ float g_el2 [NMAXN];
__device__ float g_er2 [NMAXN];
__device__ float g_e1  [(size_t)EMAXE * NH];    // slow-path scratch only
__device__ float g_e2  [EMAXE];                 // slow-path scratch only
__device__ float g_W2p [HID * C2P];
// CSR by dst
__device__ int   g_deg [NMAXN];
__device__ int   g_off [NMAXN + 1];
__device__ int   g_cur [NMAXN];
__device__ int   g_part[256];
__device__ int   g_csr_src[EMAXE];

// -------- helpers --------
__device__ __forceinline__ float lrelu(float v) { return v > 0.f ? v : 0.2f * v; }
__device__ __forceinline__ float elu(float v)   { return v > 0.f ? v : (__expf(v) - 1.f); }

// ============================================================================
// GEMM1 + fused elr1: 128x128 tile, BK=16, 8x8 register blocking
// ============================================================================
template <int K>
__global__ __launch_bounds__(256)
void gemm128_elr(const float* __restrict__ A, const float* __restrict__ W,
                 float* __restrict__ C,
                 const float* __restrict__ al, const float* __restrict__ ar,
                 int nrows)
{
    __shared__ float As[16][136];
    __shared__ float Ws[16][128];

    const int tid = threadIdx.x;
    const int tx  = tid & 15;
    const int ty  = tid >> 4;
    const int r0  = blockIdx.x * 128;

    float acc[8][8];
#pragma unroll
    for (int i = 0; i < 8; i++)
#pragma unroll
        for (int j = 0; j < 8; j++) acc[i][j] = 0.f;

    for (int kt = 0; kt < K; kt += 16) {
#pragma unroll
        for (int i = 0; i < 2; i++) {
            int idx = tid + i * 256;
            int r   = idx >> 2;
            int kq  = (idx & 3) * 4;
            float4 v = make_float4(0.f, 0.f, 0.f, 0.f);
            int row = r0 + r;
            if (row < nrows)
                v = *(const float4*)(A + (size_t)row * K + kt + kq);
            As[kq + 0][r] = v.x; As[kq + 1][r] = v.y;
            As[kq + 2][r] = v.z; As[kq + 3][r] = v.w;
        }
#pragma unroll
        for (int i = 0; i < 2; i++) {
            int idx = tid + i * 256;
            int kr  = idx >> 5;
            int cq  = (idx & 31) * 4;
            *(float4*)(&Ws[kr][cq]) =
                *(const float4*)(W + (size_t)(kt + kr) * 128 + cq);
        }
        __syncthreads();

#pragma unroll
        for (int k = 0; k < 16; k++) {
            float4 a0 = *(const float4*)(&As[k][ty * 8]);
            float4 a1 = *(const float4*)(&As[k][ty * 8 + 4]);
            float4 w0 = *(const float4*)(&Ws[k][tx * 8]);
            float4 w1 = *(const float4*)(&Ws[k][tx * 8 + 4]);
            float a[8] = {a0.x, a0.y, a0.z, a0.w, a1.x, a1.y, a1.z, a1.w};
            float w[8] = {w0.x, w0.y, w0.z, w0.w, w1.x, w1.y, w1.z, w1.w};
#pragma unroll
            for (int i = 0; i < 8; i++)
#pragma unroll
                for (int j = 0; j < 8; j++) acc[i][j] += a[i] * w[j];
        }
        __syncthreads();
    }

#pragma unroll
    for (int i = 0; i < 8; i++) {
        int row = r0 + ty * 8 + i;
        if (row >= nrows) continue;
        float* cp = C + (size_t)row * 128 + tx * 8;
        *(float4*)(cp)     = make_float4(acc[i][0], acc[i][1], acc[i][2], acc[i][3]);
        *(float4*)(cp + 4) = make_float4(acc[i][4], acc[i][5], acc[i][6], acc[i][7]);
    }

    const int lane = tid & 31;
    float alv[8], arv[8];
#pragma unroll
    for (int j = 0; j < 8; j++) {
        alv[j] = al[tx * 8 + j];
        arv[j] = ar[tx * 8 + j];
    }
    const int head = (lane & 15) >> 2;
#pragma unroll
    for (int i = 0; i < 8; i++) {
        float pel = 0.f, per = 0.f;
#pragma unroll
        for (int j = 0; j < 8; j++) {
            pel += acc[i][j] * alv[j];
            per += acc[i][j] * arv[j];
        }
        pel += __shfl_xor_sync(0xffffffffu, pel, 1);
        pel += __shfl_xor_sync(0xffffffffu, pel, 2);
        per += __shfl_xor_sync(0xffffffffu, per, 1);
        per += __shfl_xor_sync(0xffffffffu, per, 2);
        int row = r0 + ty * 8 + i;
        if ((lane & 3) == 0 && row < nrows) {
            g_el1[row * 4 + head] = pel;
            g_er1[row * 4 + head] = per;
        }
    }
}

// ============================================================================
// GEMM2 + fused elr2: writes PADDED h2 (stride C2P), stores all 64 cols
// ============================================================================
template <int K, int NC, int NCREAL>
__global__ __launch_bounds__(256)
void gemm_tiled_elr(const float* __restrict__ A, const float* __restrict__ W,
                    float* __restrict__ C,
                    const float* __restrict__ al, const float* __restrict__ ar,
                    int nrows)
{
    constexpr int CPT = NC / 32;     // 2
    __shared__ float fsh[64][32];
    __shared__ float wsh[32][NC];

    const int tid = threadIdx.x;
    const int r0  = blockIdx.x * 64;
    const int cx  = tid & 31;
    const int ry  = tid >> 5;

    float acc[8][CPT];
#pragma unroll
    for (int i = 0; i < 8; i++)
#pragma unroll
        for (int j = 0; j < CPT; j++) acc[i][j] = 0.f;

    for (int kt = 0; kt < K; kt += 32) {
#pragma unroll
        for (int i = 0; i < 2; i++) {
            int idx = tid + i * 256;
            int r = idx >> 3, kq = idx & 7;
            int row = r0 + r;
            float4 v = make_float4(0.f, 0.f, 0.f, 0.f);
            if (row < nrows)
                v = *(const float4*)(A + (size_t)row * K + kt + kq * 4);
            *(float4*)(&fsh[r][kq * 4]) = v;
        }
#pragma unroll
        for (int i = 0; i < CPT; i++) {
            int idx = tid + i * 256;
            int kr = idx / (NC / 4), cq = idx % (NC / 4);
            *(float4*)(&wsh[kr][cq * 4]) =
                *(const float4*)(W + (size_t)(kt + kr) * NC + cq * 4);
        }
        __syncthreads();

#pragma unroll
        for (int k = 0; k < 32; k++) {
            float2 wv = *(const float2*)(&wsh[k][cx * 2]);
#pragma unroll
            for (int i = 0; i < 8; i++) {
                float f = fsh[ry * 8 + i][k];
                acc[i][0] += f * wv.x;
                acc[i][1] += f * wv.y;
            }
        }
        __syncthreads();
    }

    int c0 = cx * 2, c1 = cx * 2 + 1;
    float al0 = (c0 < NCREAL) ? al[c0] : 0.f;
    float al1v = (c1 < NCREAL) ? al[c1] : 0.f;
    float ar0 = (c0 < NCREAL) ? ar[c0] : 0.f;
    float ar1v = (c1 < NCREAL) ? ar[c1] : 0.f;

#pragma unroll
    for (int i = 0; i < 8; i++) {
        int row = r0 + ry * 8 + i;
        bool ok = row < nrows;
        if (ok) {
            // store both cols (padded region holds zeros — W2p zero-padded)
            *(float2*)(C + (size_t)row * NC + c0) = make_float2(acc[i][0], acc[i][1]);
        }
        float pel = acc[i][0] * al0 + acc[i][1] * al1v;
        float per = acc[i][0] * ar0 + acc[i][1] * ar1v;
#pragma unroll
        for (int o = 16; o; o >>= 1) {
            pel += __shfl_xor_sync(0xffffffffu, pel, o);
            per += __shfl_xor_sync(0xffffffffu, per, o);
        }
        if (cx == 0 && ok) {
            g_el2[row] = pel;
            g_er2[row] = per;
        }
    }
}

// ============================================================================
// CSR build
// ============================================================================
__global__ void zero_deg(int n)
{
    int i = blockIdx.x * blockDim.x + threadIdx.x;
    if (i < n) g_deg[i] = 0;
}

__global__ void count_kernel(const int* __restrict__ dst, int e)
{
    int i = blockIdx.x * blockDim.x + threadIdx.x;
    if (i < e) atomicAdd(&g_deg[dst[i]], 1);
}

__global__ __launch_bounds__(1024)
void scan_local(int n)
{
    __shared__ int sh[1024];
    int t = threadIdx.x;
    int i = blockIdx.x * 1024 + t;
    int val = (i < n) ? g_deg[i] : 0;
    sh[t] = val;
    __syncthreads();
#pragma unroll
    for (int d = 1; d < 1024; d <<= 1) {
        int x = (t >= d) ? sh[t - d] : 0;
        __syncthreads();
        sh[t] += x;
        __syncthreads();
    }
    if (i < n) g_off[i] = sh[t] - val;
    if (t == 1023) g_part[blockIdx.x] = sh[1023];
}

__global__ void scan_part(int nblk, int n)
{
    if (threadIdx.x != 0 || blockIdx.x != 0) return;
    int run = 0;
    for (int b = 0; b < nblk; b++) {
        int v = g_part[b];
        g_part[b] = run;
        run += v;
    }
    g_off[n] = run;
}

__global__ void add_part(int n)
{
    int i = blockIdx.x * blockDim.x + threadIdx.x;
    if (i >= n) return;
    int o = g_off[i] + g_part[i >> 10];
    g_off[i] = o;
    g_cur[i] = o;
}

__global__ void scatter_kernel(const int* __restrict__ src, const int* __restrict__ dst, int e)
{
    int i = blockIdx.x * blockDim.x + threadIdx.x;
    if (i >= e) return;
    int d = dst[i];
    int pos = atomicAdd(&g_cur[d], 1);
    g_csr_src[pos] = src[i];
}

__global__ void pack_W2(const float* __restrict__ W2)
{
    int i = blockIdx.x * blockDim.x + threadIdx.x;
    if (i >= HID * C2P) return;
    int k = i / C2P, c = i % C2P;
    g_W2p[i] = (c < C2) ? W2[k * C2 + c] : 0.f;
}

// ============================================================================
// Layer 1: warp per node, register softmax fast path, 4-wide gather
// ============================================================================
__global__ __launch_bounds__(256)
void gat1_kernel(const float* __restrict__ b1, int n)
{
    __shared__ float s_alpha[8][32][4];
    __shared__ int   s_src[8][32];

    int w    = threadIdx.x >> 5;
    int node = (blockIdx.x * blockDim.x + threadIdx.x) >> 5;
    int lane = threadIdx.x & 31;
    if (node >= n) return;

    int off = g_off[node];
    int deg = g_off[node + 1] - off;
    int head = lane >> 3;

    float4 erd = *(const float4*)(g_er1 + (size_t)node * 4);
    float4 acc = make_float4(0.f, 0.f, 0.f, 0.f);

    if (deg <= 32) {
        bool valid = lane < deg;
        int s = 0;
        float4 e4 = make_float4(NEG_INF, NEG_INF, NEG_INF, NEG_INF);
        if (valid) {
            s = g_csr_src[off + lane];
            float4 a = *(const float4*)(g_el1 + (size_t)s * 4);
            e4.x = lrelu(a.x + erd.x); e4.y = lrelu(a.y + erd.y);
            e4.z = lrelu(a.z + erd.z); e4.w = lrelu(a.w + erd.w);
        }
        float4 mx = e4;
#pragma unroll
        for (int o = 16; o; o >>= 1) {
            mx.x = fmaxf(mx.x, __shfl_xor_sync(0xffffffffu, mx.x, o));
            mx.y = fmaxf(mx.y, __shfl_xor_sync(0xffffffffu, mx.y, o));
            mx.z = fmaxf(mx.z, __shfl_xor_sync(0xffffffffu, mx.z, o));
            mx.w = fmaxf(mx.w, __shfl_xor_sync(0xffffffffu, mx.w, o));
        }
        float4 ee = make_float4(0.f, 0.f, 0.f, 0.f);
        if (valid) {
            ee.x = __expf(e4.x - mx.x); ee.y = __expf(e4.y - mx.y);
            ee.z = __expf(e4.z - mx.z); ee.w = __expf(e4.w - mx.w);
        }
        float4 sm = ee;
#pragma unroll
        for (int o = 16; o; o >>= 1) {
            sm.x += __shfl_xor_sync(0xffffffffu, sm.x, o);
            sm.y += __shfl_xor_sync(0xffffffffu, sm.y, o);
            sm.z += __shfl_xor_sync(0xffffffffu, sm.z, o);
            sm.w += __shfl_xor_sync(0xffffffffu, sm.w, o);
        }
        float4 al4 = make_float4(0.f, 0.f, 0.f, 0.f);
        if (valid) {
            al4.x = ee.x / sm.x; al4.y = ee.y / sm.y;
            al4.z = ee.z / sm.z; al4.w = ee.w / sm.w;
        }
        s_src[w][lane] = s;
        *(float4*)(&s_alpha[w][lane][0]) = al4;
        __syncwarp();

        int q = 0;
        for (; q + 4 <= deg; q += 4) {
            int   s0 = s_src[w][q + 0], s1 = s_src[w][q + 1];
            int   s2 = s_src[w][q + 2], s3 = s_src[w][q + 3];
            float a0 = s_alpha[w][q + 0][head], a1 = s_alpha[w][q + 1][head];
            float a2 = s_alpha[w][q + 2][head], a3 = s_alpha[w][q + 3][head];
            float4 h0 = *(const float4*)(g_h1 + (size_t)s0 * HID + lane * 4);
            float4 h1 = *(const float4*)(g_h1 + (size_t)s1 * HID + lane * 4);
            float4 h2 = *(const float4*)(g_h1 + (size_t)s2 * HID + lane * 4);
            float4 h3 = *(const float4*)(g_h1 + (size_t)s3 * HID + lane * 4);
            acc.x += a0 * h0.x + a1 * h1.x + a2 * h2.x + a3 * h3.x;
            acc.y += a0 * h0.y + a1 * h1.y + a2 * h2.y + a3 * h3.y;
            acc.z += a0 * h0.z + a1 * h1.z + a2 * h2.z + a3 * h3.z;
            acc.w += a0 * h0.w + a1 * h1.w + a2 * h2.w + a3 * h3.w;
        }
        for (; q < deg; q++) {
            int   sq = s_src[w][q];
            float a  = s_alpha[w][q][head];
            float4 hv = *(const float4*)(g_h1 + (size_t)sq * HID + lane * 4);
            acc.x += a * hv.x; acc.y += a * hv.y;
            acc.z += a * hv.z; acc.w += a * hv.w;
        }
    } else {
        float4 mx = make_float4(NEG_INF, NEG_INF, NEG_INF, NEG_INF);
        for (int base = 0; base < deg; base += 32) {
            int j = base + lane;
            if (j < deg) {
                int s = g_csr_src[off + j];
                float4 a = *(const float4*)(g_el1 + (size_t)s * 4);
                float4 e4;
                e4.x = lrelu(a.x + erd.x); e4.y = lrelu(a.y + erd.y);
                e4.z = lrelu(a.z + erd.z); e4.w = lrelu(a.w + erd.w);
                *(float4*)(g_e1 + (size_t)(off + j) * 4) = e4;
                mx.x = fmaxf(mx.x, e4.x); mx.y = fmaxf(mx.y, e4.y);
                mx.z = fmaxf(mx.z, e4.z); mx.w = fmaxf(mx.w, e4.w);
            }
        }
#pragma unroll
        for (int o = 16; o; o >>= 1) {
            mx.x = fmaxf(mx.x, __shfl_xor_sync(0xffffffffu, mx.x, o));
            mx.y = fmaxf(mx.y, __shfl_xor_sync(0xffffffffu, mx.y, o));
            mx.z = fmaxf(mx.z, __shfl_xor_sync(0xffffffffu, mx.z, o));
            mx.w = fmaxf(mx.w, __shfl_xor_sync(0xffffffffu, mx.w, o));
        }
        float4 sm = make_float4(0.f, 0.f, 0.f, 0.f);
        for (int base = 0; base < deg; base += 32) {
            int j = base + lane;
            if (j < deg) {
                float4 e4 = *(const float4*)(g_e1 + (size_t)(off + j) * 4);
                e4.x = __expf(e4.x - mx.x); e4.y = __expf(e4.y - mx.y);
                e4.z = __expf(e4.z - mx.z); e4.w = __expf(e4.w - mx.w);
                *(float4*)(g_e1 + (size_t)(off + j) * 4) = e4;
                sm.x += e4.x; sm.y += e4.y; sm.z += e4.z; sm.w += e4.w;
            }
        }
#pragma unroll
        for (int o = 16; o; o >>= 1) {
            sm.x += __shfl_xor_sync(0xffffffffu, sm.x, o);
            sm.y += __shfl_xor_sync(0xffffffffu, sm.y, o);
            sm.z += __shfl_xor_sync(0xffffffffu, sm.z, o);
            sm.w += __shfl_xor_sync(0xffffffffu, sm.w, o);
        }
        float invh = 1.f / ((head == 0) ? sm.x : (head == 1) ? sm.y : (head == 2) ? sm.z : sm.w);

        for (int base = 0; base < deg; base += 32) {
            int cnt = min(32, deg - base);
            int j = base + lane;
            int s = 0;
            float4 ee = make_float4(0.f, 0.f, 0.f, 0.f);
            if (j < deg) {
                s = g_csr_src[off + j];
                ee = *(const float4*)(g_e1 + (size_t)(off + j) * 4);
            }
            s_src[w][lane] = s;
            *(float4*)(&s_alpha[w][lane][0]) = ee;
            __syncwarp();
            for (int q = 0; q < cnt; q++) {
                int   sq = s_src[w][q];
                float a  = s_alpha[w][q][head] * invh;
                float4 hv = *(const float4*)(g_h1 + (size_t)sq * HID + lane * 4);
                acc.x += a * hv.x; acc.y += a * hv.y;
                acc.z += a * hv.z; acc.w += a * hv.w;
            }
            __syncwarp();
        }
    }

    float4 bb = *(const float4*)(b1 + lane * 4);
    float4 o;
    o.x = elu(acc.x + bb.x); o.y = elu(acc.y + bb.y);
    o.z = elu(acc.z + bb.z); o.w = elu(acc.w + bb.w);
    *(float4*)(g_out1 + (size_t)node * HID + lane * 4) = o;
}

// ============================================================================
// Layer 2: warp per node (1 head, C=40); reads PADDED h2 (stride C2P)
// ============================================================================
__global__ __launch_bounds__(256)
void gat2_kernel(float* __restrict__ out, const float* __restrict__ b2, int n)
{
    __shared__ float s_a[8][32];
    __shared__ int   s_src[8][32];

    int w    = threadIdx.x >> 5;
    int node = (blockIdx.x * blockDim.x + threadIdx.x) >> 5;
    int lane = threadIdx.x & 31;
    if (node >= n) return;

    int off = g_off[node];
    int deg = g_off[node + 1] - off;
    float erd = g_er2[node];

    float acc0 = 0.f, acc1 = 0.f;

    if (deg <= 32) {
        bool valid = lane < deg;
        int s = 0;
        float e = NEG_INF;
        if (valid) {
            s = g_csr_src[off + lane];
            e = lrelu(g_el2[s] + erd);
        }
        float mx = e;
#pragma unroll
        for (int o = 16; o; o >>= 1)
            mx = fmaxf(mx, __shfl_xor_sync(0xffffffffu, mx, o));
        float ee = valid ? __expf(e - mx) : 0.f;
        float sm = ee;
#pragma unroll
        for (int o = 16; o; o >>= 1)
            sm += __shfl_xor_sync(0xffffffffu, sm, o);
        float alpha = valid ? (ee / sm) : 0.f;

        s_src[w][lane] = s;
        s_a[w][lane] = alpha;
        __syncwarp();

        int q = 0;
        for (; q + 4 <= deg; q += 4) {
            int   s0 = s_src[w][q + 0], s1 = s_src[w][q + 1];
            int   s2 = s_src[w][q + 2], s3 = s_src[w][q + 3];
            float a0 = s_a[w][q + 0], a1 = s_a[w][q + 1];
            float a2 = s_a[w][q + 2], a3 = s_a[w][q + 3];
            const float* p0 = g_h2 + (size_t)s0 * C2P;
            const float* p1 = g_h2 + (size_t)s1 * C2P;
            const float* p2 = g_h2 + (size_t)s2 * C2P;
            const float* p3 = g_h2 + (size_t)s3 * C2P;
            float v0 = p0[lane], v1 = p1[lane], v2 = p2[lane], v3 = p3[lane];
            acc0 += a0 * v0 + a1 * v1 + a2 * v2 + a3 * v3;
            if (lane < 8) {
                float u0 = p0[32 + lane], u1 = p1[32 + lane];
                float u2 = p2[32 + lane], u3 = p3[32 + lane];
                acc1 += a0 * u0 + a1 * u1 + a2 * u2 + a3 * u3;
            }
        }
        for (; q < deg; q++) {
            int   sq = s_src[w][q];
            float a  = s_a[w][q];
            const float* hp = g_h2 + (size_t)sq * C2P;
            acc0 += a * hp[lane];
            if (lane < 8) acc1 += a * hp[32 + lane];
        }
    } else {
        float mx = NEG_INF;
        for (int base = 0; base < deg; base += 32) {
            int j = base + lane;
            if (j < deg) {
                int s = g_csr_src[off + j];
                float e = lrelu(g_el2[s] + erd);
                g_e2[off + j] = e;
                mx = fmaxf(mx, e);
            }
        }
#pragma unroll
        for (int o = 16; o; o >>= 1)
            mx = fmaxf(mx, __shfl_xor_sync(0xffffffffu, mx, o));
        float sm = 0.f;
        for (int base = 0; base < deg; base += 32) {
            int j = base + lane;
            if (j < deg) {
                float ee = __expf(g_e2[off + j] - mx);
                g_e2[off + j] = ee;
                sm += ee;
            }
        }
#pragma unroll
        for (int o = 16; o; o >>= 1)
            sm += __shfl_xor_sync(0xffffffffu, sm, o);
        float inv = 1.f / sm;

        for (int base = 0; base < deg; base += 32) {
            int cnt = min(32, deg - base);
            int j = base + lane;
            int s = 0; float ee = 0.f;
            if (j < deg) {
                s = g_csr_src[off + j];
                ee = g_e2[off + j];
            }
            s_src[w][lane] = s;
            s_a[w][lane] = ee * inv;
            __syncwarp();
            for (int q = 0; q < cnt; q++) {
                int   sq = s_src[w][q];
                float a  = s_a[w][q];
                const float* hp = g_h2 + (size_t)sq * C2P;
                acc0 += a * hp[lane];
                if (lane < 8) acc1 += a * hp[32 + lane];
            }
            __syncwarp();
        }
    }

    out[(size_t)node * C2 + lane] = acc0 + b2[lane];
    if (lane < 8)
        out[(size_t)node * C2 + 32 + lane] = acc1 + b2[32 + lane];
}

// ============================================================================
// launch — R5 schedule: CSR ∥ gemm1 fork, then serial
// ============================================================================
extern "C" void kernel_launch(void* const* d_in, const int* in_sizes, int n_in,
                              void* d_out, int out_size)
{
    const float* feat = (const float*)d_in[0];
    const int*   src  = (const int*)  d_in[1];
    const int*   dst  = (const int*)  d_in[2];
    const float* W1   = (const float*)d_in[3];
    const float* al1  = (const float*)d_in[4];
    const float* ar1  = (const float*)d_in[5];
    const float* b1   = (const float*)d_in[6];
    const float* W2   = (const float*)d_in[7];
    const float* al2  = (const float*)d_in[8];
    const float* ar2  = (const float*)d_in[9];
    const float* b2   = (const float*)d_in[10];
    float* out = (float*)d_out;

    const int n = in_sizes[0] / INDIM;   // 100000
    const int e = in_sizes[1];           // 1600000

    float *p_h1 = 0, *p_out1 = 0, *p_h2 = 0, *p_W2p = 0;
    cudaGetSymbolAddress((void**)&p_h1,   g_h1);
    cudaGetSymbolAddress((void**)&p_out1, g_out1);
    cudaGetSymbolAddress((void**)&p_h2,   g_h2);
    cudaGetSymbolAddress((void**)&p_W2p,  g_W2p);

    static cudaStream_t s2 = 0;
    static cudaEvent_t ev_fork = 0, ev_join = 0;
    if (!s2) {
        cudaStreamCreateWithFlags(&s2, cudaStreamNonBlocking);
        cudaEventCreateWithFlags(&ev_fork, cudaEventDisableTiming);
        cudaEventCreateWithFlags(&ev_join, cudaEventDisableTiming);
    }

    const int TB = 256;
    const int nblk_scan = (n + 1023) / 1024;

    // fork: CSR build + pack_W2 on s2, concurrent with gemm1
    cudaEventRecord(ev_fork, 0);
    cudaStreamWaitEvent(s2, ev_fork, 0);

    zero_deg<<<(n + TB - 1) / TB, TB, 0, s2>>>(n);
    count_kernel<<<(e + TB - 1) / TB, TB, 0, s2>>>(dst, e);
    scan_local<<<nblk_scan, 1024, 0, s2>>>(n);
    scan_part<<<1, 32, 0, s2>>>(nblk_scan, n);
    add_part<<<(n + TB - 1) / TB, TB, 0, s2>>>(n);
    scatter_kernel<<<(e + TB - 1) / TB, TB, 0, s2>>>(src, dst, e);
    pack_W2<<<(HID * C2P + TB - 1) / TB, TB, 0, s2>>>(W2);
    cudaEventRecord(ev_join, s2);

    // default stream: layer-1 projection (+fused elr1)
    gemm128_elr<INDIM><<<(n + 127) / 128, 256>>>(feat, W1, p_h1, al1, ar1, n);
    cudaStreamWaitEvent(0, ev_join, 0);

    // serial: gat1 -> gemm2 -> gat2
    gat1_kernel<<<(n * 32 + TB - 1) / TB, TB>>>(b1, n);
    gemm_tiled_elr<HID, C2P, C2><<<(n + 63) / 64, 256>>>(p_out1, p_W2p, p_h2, al2, ar2, n);
    gat2_kernel<<<(n * 32 + TB - 1) / TB, TB>>>(out, b2, n);
}